// round 1
// baseline (speedup 1.0000x reference)
#include <cuda_runtime.h>
#include <math.h>

// Problem constants (B=8, L=2048, D=512, K=4, m=256)
#define Bn 8
#define Ln 2048
#define Dn 512
#define Kst 4
#define Mf 256
#define KLn (Kst*Ln)          // 8192
#define ROWS_Q (Bn*Ln)        // 16384
#define ROWS_K (Bn*KLn)       // 65536

__device__ float g_phi_q[(size_t)ROWS_Q * Mf];   // 16 MB
__device__ float g_phi_k[(size_t)ROWS_K * Mf];   // 64 MB
__device__ float g_sq_q[ROWS_Q];
__device__ float g_sq_k[ROWS_K];
__device__ float g_Z[Bn * Mf];
__device__ float g_S[(size_t)Bn * Mf * Dn];      // 4 MB
__device__ float g_num[(size_t)ROWS_Q * Dn];     // 32 MB

__device__ __constant__ float PROJ_SCALE = 0.21022410381342864f;  // 512^-0.25
__device__ __constant__ float SQ_SCALE   = 0.022097086912079608f; // 1/(2*sqrt(512))
__device__ __constant__ float RSQ_M      = 0.0625f;               // 256^-0.5
__device__ __constant__ float EPSV       = 1e-8f;

// ---------------------------------------------------------------------------
// Row sum-of-squares: sq[row] = sum(x^2) / (2*sqrt(D)).  One warp per row.
// ---------------------------------------------------------------------------
__global__ void rowsumsq_kernel(const float* __restrict__ X, float* __restrict__ sq, int rows)
{
    int row  = blockIdx.x * 8 + (threadIdx.x >> 5);
    int lane = threadIdx.x & 31;
    if (row >= rows) return;
    const float4* xp = (const float4*)(X + (long)row * Dn);
    float s = 0.f;
    #pragma unroll
    for (int i = lane; i < Dn / 4; i += 32) {
        float4 v = xp[i];
        s += v.x * v.x + v.y * v.y + v.z * v.z + v.w * v.w;
    }
    #pragma unroll
    for (int o = 16; o; o >>= 1) s += __shfl_xor_sync(0xffffffffu, s, o);
    if (lane == 0) sq[row] = s * SQ_SCALE;
}

// ---------------------------------------------------------------------------
// Zero S and Z
// ---------------------------------------------------------------------------
__global__ void zero_kernel(float* __restrict__ S, float* __restrict__ Z)
{
    long i = (long)blockIdx.x * 256 + threadIdx.x;
    if (i < (long)Bn * Mf * Dn) S[i] = 0.f;
    if (i < Bn * Mf)            Z[i] = 0.f;
}

// ---------------------------------------------------------------------------
// NN GEMM: C[M,N] = A[M,K] @ B[K,N].  64x64 tiles, BK=16, 256 thr, 4x4 micro.
// EPI==1: phi epilogue  C = exp(acc*PROJ_SCALE - sq[row]) * RSQ_M
// EPI==0: plain store
// grid.z indexes batch via strides.
// ---------------------------------------------------------------------------
template<int EPI>
__global__ void gemm_nn_kernel(const float* __restrict__ A,
                               const float* __restrict__ Bm,
                               float* __restrict__ C,
                               int M, int N, int Kd,
                               long strideA, long strideB, long strideC,
                               const float* __restrict__ sq)
{
    __shared__ float As[16][68];   // [k][row], padded; row base 272B (16B aligned)
    __shared__ float Bs[16][64];   // [k][col]

    int bz = blockIdx.z;
    A  += (long)bz * strideA;
    Bm += (long)bz * strideB;
    C  += (long)bz * strideC;

    int rowBlk = blockIdx.y * 64;
    int colBlk = blockIdx.x * 64;
    int tid = threadIdx.x;
    int tx = tid & 15, ty = tid >> 4;

    int arow = tid >> 2;            // 0..63
    int acol = (tid & 3) * 4;       // 0,4,8,12
    int brow = tid >> 4;            // 0..15
    int bcol = (tid & 15) * 4;      // 0..60

    float acc[4][4] = {};

    for (int k0 = 0; k0 < Kd; k0 += 16) {
        float4 av = *(const float4*)(A + (long)(rowBlk + arow) * Kd + k0 + acol);
        As[acol + 0][arow] = av.x;
        As[acol + 1][arow] = av.y;
        As[acol + 2][arow] = av.z;
        As[acol + 3][arow] = av.w;
        float4 bv = *(const float4*)(Bm + (long)(k0 + brow) * N + colBlk + bcol);
        *(float4*)&Bs[brow][bcol] = bv;
        __syncthreads();

        #pragma unroll
        for (int kk = 0; kk < 16; kk++) {
            float4 a = *(const float4*)&As[kk][ty * 4];
            float4 b = *(const float4*)&Bs[kk][tx * 4];
            float ar[4] = {a.x, a.y, a.z, a.w};
            float br[4] = {b.x, b.y, b.z, b.w};
            #pragma unroll
            for (int i = 0; i < 4; i++)
                #pragma unroll
                for (int j = 0; j < 4; j++)
                    acc[i][j] = fmaf(ar[i], br[j], acc[i][j]);
        }
        __syncthreads();
    }

    #pragma unroll
    for (int i = 0; i < 4; i++) {
        int r = rowBlk + ty * 4 + i;
        float4 o;
        if (EPI == 1) {
            float bias = sq[r];
            o.x = expf(acc[i][0] * PROJ_SCALE - bias) * RSQ_M;
            o.y = expf(acc[i][1] * PROJ_SCALE - bias) * RSQ_M;
            o.z = expf(acc[i][2] * PROJ_SCALE - bias) * RSQ_M;
            o.w = expf(acc[i][3] * PROJ_SCALE - bias) * RSQ_M;
        } else {
            o.x = acc[i][0]; o.y = acc[i][1]; o.z = acc[i][2]; o.w = acc[i][3];
        }
        *(float4*)&C[(long)r * N + colBlk + tx * 4] = o;
    }
}

// ---------------------------------------------------------------------------
// TN GEMM with split-K + atomic accumulate:
// S[b][m][d] += sum_k phi_k[b][k][m] * style[b][k][d]
// grid: (Dn/64, Mf/64, Bn*SPLITK), 256 threads. SPLITK=8 -> 1024 k each.
// ---------------------------------------------------------------------------
#define SPLITK 8
__global__ void gemm_tn_splitk_kernel(const float* __restrict__ PhiK,
                                      const float* __restrict__ Style,
                                      float* __restrict__ S)
{
    __shared__ float As[16][64];   // [k][m]
    __shared__ float Bs[16][64];   // [k][d]

    int b  = blockIdx.z / SPLITK;
    int ks = blockIdx.z % SPLITK;
    const float* A  = PhiK  + (long)b * KLn * Mf;
    const float* Bm = Style + (long)b * KLn * Dn;
    float* C        = S     + (long)b * Mf * Dn;

    int mBlk = blockIdx.y * 64;
    int dBlk = blockIdx.x * 64;
    int tid = threadIdx.x;
    int tx = tid & 15, ty = tid >> 4;

    int lrow = tid >> 4;            // 0..15 (k within tile)
    int lcol = (tid & 15) * 4;      // 0..60

    float acc[4][4] = {};

    int kBeg = ks * (KLn / SPLITK);
    int kEnd = kBeg + (KLn / SPLITK);
    for (int k0 = kBeg; k0 < kEnd; k0 += 16) {
        float4 av = *(const float4*)(A + (long)(k0 + lrow) * Mf + mBlk + lcol);
        *(float4*)&As[lrow][lcol] = av;
        float4 bv = *(const float4*)(Bm + (long)(k0 + lrow) * Dn + dBlk + lcol);
        *(float4*)&Bs[lrow][lcol] = bv;
        __syncthreads();

        #pragma unroll
        for (int kk = 0; kk < 16; kk++) {
            float4 a = *(const float4*)&As[kk][ty * 4];
            float4 b = *(const float4*)&Bs[kk][tx * 4];
            float ar[4] = {a.x, a.y, a.z, a.w};
            float br[4] = {b.x, b.y, b.z, b.w};
            #pragma unroll
            for (int i = 0; i < 4; i++)
                #pragma unroll
                for (int j = 0; j < 4; j++)
                    acc[i][j] = fmaf(ar[i], br[j], acc[i][j]);
        }
        __syncthreads();
    }

    #pragma unroll
    for (int i = 0; i < 4; i++)
        #pragma unroll
        for (int j = 0; j < 4; j++)
            atomicAdd(&C[(long)(mBlk + ty * 4 + i) * Dn + dBlk + tx * 4 + j], acc[i][j]);
}

// ---------------------------------------------------------------------------
// Z[b][m] = sum_k phi_k[b][k][m].  grid (Bn, 32), 256 threads, 256 k-rows each.
// ---------------------------------------------------------------------------
__global__ void z_kernel(const float* __restrict__ PhiK, float* __restrict__ Z)
{
    int b = blockIdx.x, chunk = blockIdx.y, m = threadIdx.x;
    const float* p = PhiK + ((long)b * KLn + (long)chunk * 256) * Mf + m;
    float s = 0.f;
    #pragma unroll 8
    for (int k = 0; k < 256; k++) s += p[(long)k * Mf];
    atomicAdd(&Z[b * Mf + m], s);
}

// ---------------------------------------------------------------------------
// Final: den = phi_q . Z + eps ; f_a = num/den ; out = (content+f_a, f_a)
// One block per (b,l) row, 128 threads.
// ---------------------------------------------------------------------------
__global__ void final_kernel(const float* __restrict__ PhiQ,
                             const float* __restrict__ Z,
                             const float* __restrict__ Num,
                             const float* __restrict__ Content,
                             float* __restrict__ Out)
{
    int row = blockIdx.x;
    int b = row / Ln;
    const float* pq = PhiQ + (long)row * Mf;
    const float* z  = Z + b * Mf;
    __shared__ float red[4];
    int tid = threadIdx.x;

    float s = pq[tid] * z[tid] + pq[tid + 128] * z[tid + 128];
    #pragma unroll
    for (int o = 16; o; o >>= 1) s += __shfl_xor_sync(0xffffffffu, s, o);
    if ((tid & 31) == 0) red[tid >> 5] = s;
    __syncthreads();
    float den = red[0] + red[1] + red[2] + red[3] + EPSV;
    float inv = 1.0f / den;

    const float* nrow = Num + (long)row * Dn;
    const float* crow = Content + (long)row * Dn;
    float* o1 = Out + (long)row * Dn;
    float* o2 = Out + (long)ROWS_Q * Dn + (long)row * Dn;
    #pragma unroll
    for (int d = tid; d < Dn; d += 128) {
        float fa = nrow[d] * inv;
        o1[d] = crow[d] + fa;
        o2[d] = fa;
    }
}

// ---------------------------------------------------------------------------
// Launch
// ---------------------------------------------------------------------------
extern "C" void kernel_launch(void* const* d_in, const int* in_sizes, int n_in,
                              void* d_out, int out_size)
{
    const float* content = (const float*)d_in[0];
    const float* style   = (const float*)d_in[1];
    const float* W       = (const float*)d_in[2];
    float* out = (float*)d_out;

    float *phi_q, *phi_k, *sqq, *sqk, *Z, *S, *num;
    cudaGetSymbolAddress((void**)&phi_q, g_phi_q);
    cudaGetSymbolAddress((void**)&phi_k, g_phi_k);
    cudaGetSymbolAddress((void**)&sqq,   g_sq_q);
    cudaGetSymbolAddress((void**)&sqk,   g_sq_k);
    cudaGetSymbolAddress((void**)&Z,     g_Z);
    cudaGetSymbolAddress((void**)&S,     g_S);
    cudaGetSymbolAddress((void**)&num,   g_num);

    // 1) row sum-of-squares
    rowsumsq_kernel<<<ROWS_Q / 8, 256>>>(content, sqq, ROWS_Q);
    rowsumsq_kernel<<<ROWS_K / 8, 256>>>(style, sqk, ROWS_K);

    // 2) zero S and Z
    zero_kernel<<<(Bn * Mf * Dn) / 256, 256>>>(S, Z);

    // 3) phi_q = phi(content @ W)   M=16384 N=256 K=512
    {
        dim3 g(Mf / 64, ROWS_Q / 64, 1);
        gemm_nn_kernel<1><<<g, 256>>>(content, W, phi_q, ROWS_Q, Mf, Dn, 0, 0, 0, sqq);
    }
    // 4) phi_k = phi(style @ W)     M=65536 N=256 K=512
    {
        dim3 g(Mf / 64, ROWS_K / 64, 1);
        gemm_nn_kernel<1><<<g, 256>>>(style, W, phi_k, ROWS_K, Mf, Dn, 0, 0, 0, sqk);
    }
    // 5) Z = colsum(phi_k) per batch
    z_kernel<<<dim3(Bn, 32), 256>>>(phi_k, Z);

    // 6) S[b] = phi_k[b]^T @ style[b]  (split-K atomics)
    {
        dim3 g(Dn / 64, Mf / 64, Bn * SPLITK);
        gemm_tn_splitk_kernel<<<g, 256>>>(phi_k, style, S);
    }
    // 7) num[b] = phi_q[b] @ S[b]   M=2048 N=512 K=256 per batch
    {
        dim3 g(Dn / 64, Ln / 64, Bn);
        gemm_nn_kernel<0><<<g, 256>>>(phi_q, S, num, Ln, Dn, Mf,
                                      (long)Ln * Mf, (long)Mf * Dn, (long)Ln * Dn, nullptr);
    }
    // 8) den + divide + outputs
    final_kernel<<<ROWS_Q, 128>>>(phi_q, Z, num, content, out);
}